// round 2
// baseline (speedup 1.0000x reference)
#include <cuda_runtime.h>

#define WSZ 7
#define SHIFT 3
#define HEADS 16
#define NTOK 49            // 7*7
#define CDIM 512
#define DHEAD 32
#define HH 56
#define NWIN 1024          // B(16) * 64 windows
#define MROWS (NWIN*NTOK)  // 50176

// scratch (no allocations allowed): qkv in [s][win][head][tok][d] layout, attn output row-major
__device__ float g_qkv[(size_t)3*NWIN*HEADS*NTOK*DHEAD];   // ~308 MB
__device__ float g_attnout[(size_t)MROWS*CDIM];            // ~103 MB

// window-token row -> pixel offset in the ORIGINAL (unshifted) image.
// shifted img xs[hs,ws] = x[(hs+3)%56, (ws+3)%56]; window partition over xs.
__device__ __forceinline__ int row_to_pixel(int r) {
    int win = r / NTOK, t = r - win * NTOK;
    int b  = win >> 6;
    int wy = (win >> 3) & 7;
    int wx = win & 7;
    int ty = t / WSZ, tx = t - ty * WSZ;
    int hs = wy * WSZ + ty;
    int ws = wx * WSZ + tx;
    int h = hs + SHIFT; if (h >= HH) h -= HH;
    int w = ws + SHIFT; if (w >= HH) w -= HH;
    return (b * HH + h) * HH + w;
}

// ---------------------------------------------------------------------------
// Kernel 1: QKV GEMM.  A = gathered x rows [50176 x 512], B = qkv_w [512 x 1536]
// C written into g_qkv with [s][win][head][tok][d] layout. 128x128x8 tile, 8x8/thread.
// ---------------------------------------------------------------------------
__global__ __launch_bounds__(256) void qkv_gemm(const float* __restrict__ x,
                                                const float* __restrict__ w,
                                                const float* __restrict__ bias) {
    __shared__ float As[8][128];
    __shared__ float Bs[8][128];
    __shared__ int rowoff[128];

    const int tid  = threadIdx.x;
    const int row0 = blockIdx.y * 128;
    const int col0 = blockIdx.x * 128;

    if (tid < 128) rowoff[tid] = row_to_pixel(row0 + tid) * CDIM;

    float acc[8][8];
#pragma unroll
    for (int i = 0; i < 8; i++)
#pragma unroll
        for (int j = 0; j < 8; j++) acc[i][j] = 0.0f;

    const int arow = tid >> 1, ak = (tid & 1) * 4;
    const int brow = tid >> 5, bcol = (tid & 31) * 4;
    const int ty = tid >> 4, tx = tid & 15;

    __syncthreads();

    for (int kt = 0; kt < CDIM; kt += 8) {
        float4 av = *reinterpret_cast<const float4*>(x + rowoff[arow] + kt + ak);
        float4 bv = *reinterpret_cast<const float4*>(w + (size_t)(kt + brow) * 1536 + col0 + bcol);
        As[ak + 0][arow] = av.x;
        As[ak + 1][arow] = av.y;
        As[ak + 2][arow] = av.z;
        As[ak + 3][arow] = av.w;
        *reinterpret_cast<float4*>(&Bs[brow][bcol]) = bv;
        __syncthreads();
#pragma unroll
        for (int k = 0; k < 8; k++) {
            float rm[8], rn[8];
#pragma unroll
            for (int i = 0; i < 8; i++) rm[i] = As[k][ty * 8 + i];
#pragma unroll
            for (int j = 0; j < 8; j++) rn[j] = Bs[k][tx * 8 + j];
#pragma unroll
            for (int i = 0; i < 8; i++)
#pragma unroll
                for (int j = 0; j < 8; j++) acc[i][j] += rm[i] * rn[j];
        }
        __syncthreads();
    }

    // scatter into [s][win][head][tok][d]
#pragma unroll
    for (int i = 0; i < 8; i++) {
        int r = row0 + ty * 8 + i;
        int win = r / NTOK, t = r - win * NTOK;
#pragma unroll
        for (int j = 0; j < 8; j++) {
            int c = col0 + tx * 8 + j;
            int s = c >> 9;
            int head = (c >> 5) & 15;
            int dd = c & 31;
            size_t oidx = (((size_t)s * NWIN + win) * HEADS + head) * (NTOK * DHEAD)
                        + (size_t)t * DHEAD + dd;
            g_qkv[oidx] = acc[i][j] + bias[c];
        }
    }
}

// ---------------------------------------------------------------------------
// Kernel 2: windowed attention, one block per (window, head). 128 threads.
// ---------------------------------------------------------------------------
__global__ __launch_bounds__(128) void attn_kernel(const float* __restrict__ table) {
    const int wh = blockIdx.x;
    const int win = wh >> 4;
    const int head = wh & 15;
    const int tid = threadIdx.x;

    __shared__ float qs[NTOK * 33];
    __shared__ float ks[NTOK * 33];
    __shared__ float vs[NTOK * 33];
    __shared__ float S[NTOK * NTOK];
    __shared__ float tbl[169];
    __shared__ int reg[NTOK];

    const size_t SOFF = (size_t)NWIN * HEADS * NTOK * DHEAD;
    const size_t base = ((size_t)win * HEADS + head) * (NTOK * DHEAD);

    for (int idx = tid; idx < NTOK * DHEAD; idx += 128) {
        int t = idx >> 5, dd = idx & 31;
        qs[t * 33 + dd] = g_qkv[base + idx];
        ks[t * 33 + dd] = g_qkv[SOFF + base + idx];
        vs[t * 33 + dd] = g_qkv[2 * SOFF + base + idx];
    }
    for (int idx = tid; idx < 169; idx += 128) tbl[idx] = table[idx * HEADS + head];
    if (tid < NTOK) {
        int wy = (win >> 3) & 7, wx = win & 7;
        int ty = tid / WSZ, tx = tid - ty * WSZ;
        int hs = wy * WSZ + ty, ws = wx * WSZ + tx;
        int rh = (hs < 49) ? 0 : ((hs < 53) ? 1 : 2);
        int rw = (ws < 49) ? 0 : ((ws < 53) ? 1 : 2);
        reg[tid] = rh * 3 + rw;
    }
    __syncthreads();

    const float scale = 0.17677669529663687f;  // 32^-0.5

    for (int idx = tid; idx < NTOK * NTOK; idx += 128) {
        int i = idx / NTOK, j = idx - i * NTOK;
        float dot = 0.0f;
#pragma unroll
        for (int dd = 0; dd < 32; dd++) dot += qs[i * 33 + dd] * ks[j * 33 + dd];
        int iy = i / WSZ, ix = i - iy * WSZ;
        int jy = j / WSZ, jx = j - jy * WSZ;
        int ridx = (iy - jy + 6) * 13 + (ix - jx + 6);
        float m = (reg[i] != reg[j]) ? -100.0f : 0.0f;
        S[idx] = dot * scale + tbl[ridx] + m;
    }
    __syncthreads();

    if (tid < NTOK) {
        float mx = -1e30f;
#pragma unroll
        for (int j = 0; j < NTOK; j++) mx = fmaxf(mx, S[tid * NTOK + j]);
        float sum = 0.0f;
#pragma unroll
        for (int j = 0; j < NTOK; j++) {
            float e = __expf(S[tid * NTOK + j] - mx);
            S[tid * NTOK + j] = e;
            sum += e;
        }
        float inv = 1.0f / sum;
#pragma unroll
        for (int j = 0; j < NTOK; j++) S[tid * NTOK + j] *= inv;
    }
    __syncthreads();

    for (int idx = tid; idx < NTOK * DHEAD; idx += 128) {
        int i = idx >> 5, dd = idx & 31;
        float o = 0.0f;
#pragma unroll
        for (int j = 0; j < NTOK; j++) o += S[i * NTOK + j] * vs[j * 33 + dd];
        g_attnout[((size_t)win * NTOK + i) * CDIM + head * DHEAD + dd] = o;
    }
}

// ---------------------------------------------------------------------------
// Kernel 3: proj GEMM + window reverse + un-shift + bias + residual.
// A = g_attnout [50176 x 512] row-major, B = proj_w [512 x 512].
// ---------------------------------------------------------------------------
__global__ __launch_bounds__(256) void proj_gemm(const float* __restrict__ x,
                                                 const float* __restrict__ w,
                                                 const float* __restrict__ bias,
                                                 float* __restrict__ out) {
    __shared__ float As[8][128];
    __shared__ float Bs[8][128];

    const int tid  = threadIdx.x;
    const int row0 = blockIdx.y * 128;
    const int col0 = blockIdx.x * 128;

    float acc[8][8];
#pragma unroll
    for (int i = 0; i < 8; i++)
#pragma unroll
        for (int j = 0; j < 8; j++) acc[i][j] = 0.0f;

    const int arow = tid >> 1, ak = (tid & 1) * 4;
    const int brow = tid >> 5, bcol = (tid & 31) * 4;
    const int ty = tid >> 4, tx = tid & 15;

    for (int kt = 0; kt < CDIM; kt += 8) {
        float4 av = *reinterpret_cast<const float4*>(
            g_attnout + (size_t)(row0 + arow) * CDIM + kt + ak);
        float4 bv = *reinterpret_cast<const float4*>(
            w + (size_t)(kt + brow) * CDIM + col0 + bcol);
        As[ak + 0][arow] = av.x;
        As[ak + 1][arow] = av.y;
        As[ak + 2][arow] = av.z;
        As[ak + 3][arow] = av.w;
        *reinterpret_cast<float4*>(&Bs[brow][bcol]) = bv;
        __syncthreads();
#pragma unroll
        for (int k = 0; k < 8; k++) {
            float rm[8], rn[8];
#pragma unroll
            for (int i = 0; i < 8; i++) rm[i] = As[k][ty * 8 + i];
#pragma unroll
            for (int j = 0; j < 8; j++) rn[j] = Bs[k][tx * 8 + j];
#pragma unroll
            for (int i = 0; i < 8; i++)
#pragma unroll
                for (int j = 0; j < 8; j++) acc[i][j] += rm[i] * rn[j];
        }
        __syncthreads();
    }

#pragma unroll
    for (int i = 0; i < 8; i++) {
        int r = row0 + ty * 8 + i;
        size_t pix = (size_t)row_to_pixel(r) * CDIM;
#pragma unroll
        for (int j = 0; j < 8; j++) {
            int c = col0 + tx * 8 + j;
            out[pix + c] = x[pix + c] + acc[i][j] + bias[c];
        }
    }
}

extern "C" void kernel_launch(void* const* d_in, const int* in_sizes, int n_in,
                              void* d_out, int out_size) {
    const float* x      = (const float*)d_in[0];
    const float* qkv_w  = (const float*)d_in[1];
    const float* qkv_b  = (const float*)d_in[2];
    const float* proj_w = (const float*)d_in[3];
    const float* proj_b = (const float*)d_in[4];
    const float* table  = (const float*)d_in[5];
    float* out = (float*)d_out;

    dim3 g1(1536 / 128, MROWS / 128);   // 12 x 392
    qkv_gemm<<<g1, 256>>>(x, qkv_w, qkv_b);

    attn_kernel<<<NWIN * HEADS, 128>>>(table);

    dim3 g3(CDIM / 128, MROWS / 128);   // 4 x 392
    proj_gemm<<<g3, 256>>>(x, proj_w, proj_b, out);
}

// round 3
// speedup vs baseline: 1.2314x; 1.2314x over previous
#include <cuda_runtime.h>

#define WSZ 7
#define SHIFT 3
#define HEADS 16
#define NTOK 49
#define CDIM 512
#define DHEAD 32
#define HH 56
#define NWIN 1024
#define MROWS (NWIN*NTOK)  // 50176

typedef unsigned long long ull;

__device__ float g_qkv[(size_t)3*NWIN*HEADS*NTOK*DHEAD];
__device__ float g_attnout[(size_t)MROWS*CDIM];

__device__ __forceinline__ int row_to_pixel(int r) {
    int win = r / NTOK, t = r - win * NTOK;
    int b  = win >> 6;
    int wy = (win >> 3) & 7;
    int wx = win & 7;
    int ty = t / WSZ, tx = t - ty * WSZ;
    int hs = wy * WSZ + ty;
    int ws = wx * WSZ + tx;
    int h = hs + SHIFT; if (h >= HH) h -= HH;
    int w = ws + SHIFT; if (w >= HH) w -= HH;
    return (b * HH + h) * HH + w;
}

// ---- packed f32x2 helpers (FFMA2) -----------------------------------------
__device__ __forceinline__ ull pack2(float x) {
    ull r; asm("mov.b64 %0, {%1, %1};" : "=l"(r) : "f"(x)); return r;
}
__device__ __forceinline__ void fma2(ull& d, ull a, ull b) {
    asm("fma.rn.f32x2 %0, %1, %2, %3;" : "=l"(d) : "l"(a), "l"(b), "l"(d));
}
__device__ __forceinline__ float2 unpack2(ull v) {
    float2 f; asm("mov.b64 {%0, %1}, %2;" : "=f"(f.x), "=f"(f.y) : "l"(v)); return f;
}

// ---------------------------------------------------------------------------
// Kernel 1: QKV GEMM (gathered rows) -> g_qkv [s][win][head][tok][d]
// 128x128x8 tile, 256 threads, 8x8/thread via FFMA2, double-buffered smem.
// ---------------------------------------------------------------------------
__global__ __launch_bounds__(256) void qkv_gemm(const float* __restrict__ x,
                                                const float* __restrict__ w,
                                                const float* __restrict__ bias) {
    __shared__ float As[2][8][128];
    __shared__ float Bs[2][8][128];
    __shared__ int rowoff[128];

    const int tid  = threadIdx.x;
    const int row0 = blockIdx.y * 128;
    const int col0 = blockIdx.x * 128;

    if (tid < 128) rowoff[tid] = row_to_pixel(row0 + tid) * CDIM;

    ull acc[8][4];
#pragma unroll
    for (int i = 0; i < 8; i++)
#pragma unroll
        for (int j = 0; j < 4; j++) acc[i][j] = 0ull;

    const int arow = tid >> 1, ak = (tid & 1) * 4;
    const int brow = tid >> 5, bcol = (tid & 31) * 4;
    const int ty = tid >> 4, tx = tid & 15;

    __syncthreads();

    // preload tile 0
    float4 av = *reinterpret_cast<const float4*>(x + rowoff[arow] + ak);
    float4 bv = *reinterpret_cast<const float4*>(w + (size_t)brow * 1536 + col0 + bcol);
    As[0][ak + 0][arow] = av.x; As[0][ak + 1][arow] = av.y;
    As[0][ak + 2][arow] = av.z; As[0][ak + 3][arow] = av.w;
    *reinterpret_cast<float4*>(&Bs[0][brow][bcol]) = bv;
    __syncthreads();

#pragma unroll 1
    for (int t = 0; t < 64; t++) {
        const int b = t & 1;
        if (t < 63) {
            const int kt = (t + 1) * 8;
            av = *reinterpret_cast<const float4*>(x + rowoff[arow] + kt + ak);
            bv = *reinterpret_cast<const float4*>(w + (size_t)(kt + brow) * 1536 + col0 + bcol);
        }
#pragma unroll
        for (int k = 0; k < 8; k++) {
            float4 a0 = *reinterpret_cast<const float4*>(&As[b][k][ty * 8]);
            float4 a1 = *reinterpret_cast<const float4*>(&As[b][k][ty * 8 + 4]);
            ull b0 = *reinterpret_cast<const ull*>(&Bs[b][k][tx * 4]);
            ull b1 = *reinterpret_cast<const ull*>(&Bs[b][k][tx * 4 + 2]);
            ull b2 = *reinterpret_cast<const ull*>(&Bs[b][k][64 + tx * 4]);
            ull b3 = *reinterpret_cast<const ull*>(&Bs[b][k][64 + tx * 4 + 2]);
            float rm[8] = {a0.x, a0.y, a0.z, a0.w, a1.x, a1.y, a1.z, a1.w};
#pragma unroll
            for (int i = 0; i < 8; i++) {
                ull am = pack2(rm[i]);
                fma2(acc[i][0], am, b0);
                fma2(acc[i][1], am, b1);
                fma2(acc[i][2], am, b2);
                fma2(acc[i][3], am, b3);
            }
        }
        if (t < 63) {
            const int nb = b ^ 1;
            As[nb][ak + 0][arow] = av.x; As[nb][ak + 1][arow] = av.y;
            As[nb][ak + 2][arow] = av.z; As[nb][ak + 3][arow] = av.w;
            *reinterpret_cast<float4*>(&Bs[nb][brow][bcol]) = bv;
            __syncthreads();
        }
    }

    // scatter into [s][win][head][tok][d], float4 stores
#pragma unroll
    for (int i = 0; i < 8; i++) {
        int r = row0 + ty * 8 + i;
        int win = r / NTOK, tok = r - win * NTOK;
#pragma unroll
        for (int h = 0; h < 2; h++) {
            int c = col0 + h * 64 + tx * 4;
            float2 lo = unpack2(acc[i][2 * h]);
            float2 hi = unpack2(acc[i][2 * h + 1]);
            int s = c >> 9;
            int head = (c >> 5) & 15;
            int dd = c & 31;
            size_t oidx = (((size_t)s * NWIN + win) * HEADS + head) * (NTOK * DHEAD)
                        + (size_t)tok * DHEAD + dd;
            float4 bv4 = *reinterpret_cast<const float4*>(bias + c);
            float4 ov = {lo.x + bv4.x, lo.y + bv4.y, hi.x + bv4.z, hi.y + bv4.w};
            *reinterpret_cast<float4*>(&g_qkv[oidx]) = ov;
        }
    }
}

// ---------------------------------------------------------------------------
// Kernel 2: windowed attention, one block per (window, head). 256 threads.
// ---------------------------------------------------------------------------
__global__ __launch_bounds__(256) void attn_kernel(const float* __restrict__ table) {
    const int wh = blockIdx.x;
    const int win = wh >> 4;
    const int head = wh & 15;
    const int tid = threadIdx.x;

    __shared__ float qs[NTOK * 33];
    __shared__ float ks[NTOK * 33];
    __shared__ float vs[NTOK * 33];
    __shared__ float S[NTOK * NTOK];
    __shared__ float tbl[169];
    __shared__ int reg[NTOK];

    const size_t SOFF = (size_t)NWIN * HEADS * NTOK * DHEAD;
    const size_t base = ((size_t)win * HEADS + head) * (NTOK * DHEAD);

    for (int idx = tid; idx < NTOK * DHEAD; idx += 256) {
        int t = idx >> 5, dd = idx & 31;
        qs[t * 33 + dd] = g_qkv[base + idx];
        ks[t * 33 + dd] = g_qkv[SOFF + base + idx];
        vs[t * 33 + dd] = g_qkv[2 * SOFF + base + idx];
    }
    if (tid < 169) tbl[tid] = table[tid * HEADS + head];
    if (tid >= 192 && tid < 192 + NTOK) {
        int t = tid - 192;
        int wy = (win >> 3) & 7, wx = win & 7;
        int ty = t / WSZ, tx = t - ty * WSZ;
        int hs = wy * WSZ + ty, ws = wx * WSZ + tx;
        int rh = (hs < 49) ? 0 : ((hs < 53) ? 1 : 2);
        int rw = (ws < 49) ? 0 : ((ws < 53) ? 1 : 2);
        reg[t] = rh * 3 + rw;
    }
    __syncthreads();

    const float scale = 0.17677669529663687f;

    for (int idx = tid; idx < NTOK * NTOK; idx += 256) {
        int i = idx / NTOK, j = idx - i * NTOK;
        float d0 = 0.0f, d1 = 0.0f;
#pragma unroll
        for (int dd = 0; dd < 32; dd += 2) {
            d0 += qs[i * 33 + dd]     * ks[j * 33 + dd];
            d1 += qs[i * 33 + dd + 1] * ks[j * 33 + dd + 1];
        }
        int iy = i / WSZ, ix = i - iy * WSZ;
        int jy = j / WSZ, jx = j - jy * WSZ;
        int ridx = (iy - jy + 6) * 13 + (ix - jx + 6);
        float m = (reg[i] != reg[j]) ? -100.0f : 0.0f;
        S[idx] = (d0 + d1) * scale + tbl[ridx] + m;
    }
    __syncthreads();

    if (tid < NTOK) {
        float mx = -1e30f;
#pragma unroll
        for (int j = 0; j < NTOK; j++) mx = fmaxf(mx, S[tid * NTOK + j]);
        float sum = 0.0f;
#pragma unroll
        for (int j = 0; j < NTOK; j++) {
            float e = __expf(S[tid * NTOK + j] - mx);
            S[tid * NTOK + j] = e;
            sum += e;
        }
        float inv = 1.0f / sum;
#pragma unroll
        for (int j = 0; j < NTOK; j++) S[tid * NTOK + j] *= inv;
    }
    __syncthreads();

    for (int idx = tid; idx < NTOK * DHEAD; idx += 256) {
        int i = idx >> 5, dd = idx & 31;
        float o0 = 0.0f, o1 = 0.0f;
#pragma unroll
        for (int j = 0; j < 48; j += 2) {
            o0 += S[i * NTOK + j]     * vs[j * 33 + dd];
            o1 += S[i * NTOK + j + 1] * vs[(j + 1) * 33 + dd];
        }
        o0 += S[i * NTOK + 48] * vs[48 * 33 + dd];
        g_attnout[((size_t)win * NTOK + i) * CDIM + head * DHEAD + dd] = o0 + o1;
    }
}

// ---------------------------------------------------------------------------
// Kernel 3: proj GEMM + window reverse + un-shift + bias + residual
// ---------------------------------------------------------------------------
__global__ __launch_bounds__(256) void proj_gemm(const float* __restrict__ x,
                                                 const float* __restrict__ w,
                                                 const float* __restrict__ bias,
                                                 float* __restrict__ out) {
    __shared__ float As[2][8][128];
    __shared__ float Bs[2][8][128];

    const int tid  = threadIdx.x;
    const int row0 = blockIdx.y * 128;
    const int col0 = blockIdx.x * 128;

    ull acc[8][4];
#pragma unroll
    for (int i = 0; i < 8; i++)
#pragma unroll
        for (int j = 0; j < 4; j++) acc[i][j] = 0ull;

    const int arow = tid >> 1, ak = (tid & 1) * 4;
    const int brow = tid >> 5, bcol = (tid & 31) * 4;
    const int ty = tid >> 4, tx = tid & 15;

    float4 av = *reinterpret_cast<const float4*>(
        g_attnout + (size_t)(row0 + arow) * CDIM + ak);
    float4 bv = *reinterpret_cast<const float4*>(
        w + (size_t)brow * CDIM + col0 + bcol);
    As[0][ak + 0][arow] = av.x; As[0][ak + 1][arow] = av.y;
    As[0][ak + 2][arow] = av.z; As[0][ak + 3][arow] = av.w;
    *reinterpret_cast<float4*>(&Bs[0][brow][bcol]) = bv;
    __syncthreads();

#pragma unroll 1
    for (int t = 0; t < 64; t++) {
        const int b = t & 1;
        if (t < 63) {
            const int kt = (t + 1) * 8;
            av = *reinterpret_cast<const float4*>(
                g_attnout + (size_t)(row0 + arow) * CDIM + kt + ak);
            bv = *reinterpret_cast<const float4*>(
                w + (size_t)(kt + brow) * CDIM + col0 + bcol);
        }
#pragma unroll
        for (int k = 0; k < 8; k++) {
            float4 a0 = *reinterpret_cast<const float4*>(&As[b][k][ty * 8]);
            float4 a1 = *reinterpret_cast<const float4*>(&As[b][k][ty * 8 + 4]);
            ull b0 = *reinterpret_cast<const ull*>(&Bs[b][k][tx * 4]);
            ull b1 = *reinterpret_cast<const ull*>(&Bs[b][k][tx * 4 + 2]);
            ull b2 = *reinterpret_cast<const ull*>(&Bs[b][k][64 + tx * 4]);
            ull b3 = *reinterpret_cast<const ull*>(&Bs[b][k][64 + tx * 4 + 2]);
            float rm[8] = {a0.x, a0.y, a0.z, a0.w, a1.x, a1.y, a1.z, a1.w};
#pragma unroll
            for (int i = 0; i < 8; i++) {
                ull am = pack2(rm[i]);
                fma2(acc[i][0], am, b0);
                fma2(acc[i][1], am, b1);
                fma2(acc[i][2], am, b2);
                fma2(acc[i][3], am, b3);
            }
        }
        if (t < 63) {
            const int nb = b ^ 1;
            As[nb][ak + 0][arow] = av.x; As[nb][ak + 1][arow] = av.y;
            As[nb][ak + 2][arow] = av.z; As[nb][ak + 3][arow] = av.w;
            *reinterpret_cast<float4*>(&Bs[nb][brow][bcol]) = bv;
            __syncthreads();
        }
    }

#pragma unroll
    for (int i = 0; i < 8; i++) {
        int r = row0 + ty * 8 + i;
        size_t pix = (size_t)row_to_pixel(r) * CDIM;
#pragma unroll
        for (int h = 0; h < 2; h++) {
            int c = col0 + h * 64 + tx * 4;
            float2 lo = unpack2(acc[i][2 * h]);
            float2 hi = unpack2(acc[i][2 * h + 1]);
            float4 bv4 = *reinterpret_cast<const float4*>(bias + c);
            float4 xv  = *reinterpret_cast<const float4*>(x + pix + c);
            float4 ov = {xv.x + lo.x + bv4.x, xv.y + lo.y + bv4.y,
                         xv.z + hi.x + bv4.z, xv.w + hi.y + bv4.w};
            *reinterpret_cast<float4*>(&out[pix + c]) = ov;
        }
    }
}

extern "C" void kernel_launch(void* const* d_in, const int* in_sizes, int n_in,
                              void* d_out, int out_size) {
    const float* x      = (const float*)d_in[0];
    const float* qkv_w  = (const float*)d_in[1];
    const float* qkv_b  = (const float*)d_in[2];
    const float* proj_w = (const float*)d_in[3];
    const float* proj_b = (const float*)d_in[4];
    const float* table  = (const float*)d_in[5];
    float* out = (float*)d_out;

    dim3 g1(1536 / 128, MROWS / 128);
    qkv_gemm<<<g1, 256>>>(x, qkv_w, qkv_b);

    attn_kernel<<<NWIN * HEADS, 256>>>(table);

    dim3 g3(CDIM / 128, MROWS / 128);
    proj_gemm<<<g3, 256>>>(x, proj_w, proj_b, out);
}

// round 4
// speedup vs baseline: 2.6873x; 2.1824x over previous
#include <cuda_runtime.h>

#define WSZ 7
#define SHIFT 3
#define HEADS 16
#define NTOK 49
#define CDIM 512
#define DHEAD 32
#define HH 56
#define NWIN 1024
#define MROWS (NWIN*NTOK)  // 50176

__device__ float g_qkv[(size_t)3*NWIN*HEADS*NTOK*DHEAD];
__device__ float g_attnout[(size_t)MROWS*CDIM];

__device__ __forceinline__ int row_to_pixel(int r) {
    int win = r / NTOK, t = r - win * NTOK;
    int b  = win >> 6;
    int wy = (win >> 3) & 7;
    int wx = win & 7;
    int ty = t / WSZ, tx = t - ty * WSZ;
    int hs = wy * WSZ + ty;
    int ws = wx * WSZ + tx;
    int h = hs + SHIFT; if (h >= HH) h -= HH;
    int w = ws + SHIFT; if (w >= HH) w -= HH;
    return (b * HH + h) * HH + w;
}

__device__ __forceinline__ unsigned f2tf(float f) {
    unsigned r; asm("cvt.rna.tf32.f32 %0, %1;" : "=r"(r) : "f"(f)); return r;
}

__device__ __forceinline__ void mma_tf32(float* d, const unsigned* a, const unsigned* b) {
    asm volatile(
        "mma.sync.aligned.m16n8k8.row.col.f32.tf32.tf32.f32 "
        "{%0,%1,%2,%3}, {%4,%5,%6,%7}, {%8,%9}, {%0,%1,%2,%3};"
        : "+f"(d[0]), "+f"(d[1]), "+f"(d[2]), "+f"(d[3])
        : "r"(a[0]), "r"(a[1]), "r"(a[2]), "r"(a[3]), "r"(b[0]), "r"(b[1]));
}

#define SMS 136  // smem row stride: (8k+m)%32 conflict-free

// ---------------------------------------------------------------------------
// Kernel 1: QKV GEMM via mma.sync tf32. 128x128x16 tile, 256 thr, 8 warps 2x4.
// ---------------------------------------------------------------------------
__global__ __launch_bounds__(256, 1) void qkv_gemm(const float* __restrict__ x,
                                                   const float* __restrict__ w,
                                                   const float* __restrict__ bias) {
    __shared__ unsigned As[2][16][SMS];
    __shared__ unsigned Bs[2][16][SMS];
    __shared__ int rowoff[128];

    const int tid  = threadIdx.x;
    const int row0 = blockIdx.y * 128;
    const int col0 = blockIdx.x * 128;
    const int lane = tid & 31, wid = tid >> 5;
    const int wm = wid >> 2, wn = wid & 3;

    if (tid < 128) rowoff[tid] = row_to_pixel(row0 + tid) * CDIM;

    float acc[16][4];
#pragma unroll
    for (int i = 0; i < 16; i++)
#pragma unroll
        for (int j = 0; j < 4; j++) acc[i][j] = 0.0f;

    const int arow = tid & 127, ak0 = (tid >> 7) * 8;
    const int brow = tid >> 4,  bcol = (tid & 15) * 8;

    __syncthreads();

    // preload tile 0
    float4 av0 = *reinterpret_cast<const float4*>(x + rowoff[arow] + ak0);
    float4 av1 = *reinterpret_cast<const float4*>(x + rowoff[arow] + ak0 + 4);
    float4 bv0 = *reinterpret_cast<const float4*>(w + (size_t)brow * 1536 + col0 + bcol);
    float4 bv1 = *reinterpret_cast<const float4*>(w + (size_t)brow * 1536 + col0 + bcol + 4);
    {
        float af[8] = {av0.x,av0.y,av0.z,av0.w,av1.x,av1.y,av1.z,av1.w};
#pragma unroll
        for (int i = 0; i < 8; i++) As[0][ak0 + i][arow] = f2tf(af[i]);
        uint4 p0 = {f2tf(bv0.x),f2tf(bv0.y),f2tf(bv0.z),f2tf(bv0.w)};
        uint4 p1 = {f2tf(bv1.x),f2tf(bv1.y),f2tf(bv1.z),f2tf(bv1.w)};
        *reinterpret_cast<uint4*>(&Bs[0][brow][bcol])     = p0;
        *reinterpret_cast<uint4*>(&Bs[0][brow][bcol + 4]) = p1;
    }
    __syncthreads();

    const int mbase = wm * 64 + (lane >> 2);
    const int nbase = wn * 32 + (lane >> 2);

#pragma unroll 1
    for (int t = 0; t < 32; t++) {
        const int b = t & 1;
        if (t < 31) {
            const int kt = (t + 1) * 16;
            av0 = *reinterpret_cast<const float4*>(x + rowoff[arow] + kt + ak0);
            av1 = *reinterpret_cast<const float4*>(x + rowoff[arow] + kt + ak0 + 4);
            bv0 = *reinterpret_cast<const float4*>(w + (size_t)(kt + brow) * 1536 + col0 + bcol);
            bv1 = *reinterpret_cast<const float4*>(w + (size_t)(kt + brow) * 1536 + col0 + bcol + 4);
        }
#pragma unroll
        for (int ks = 0; ks < 2; ks++) {
            const int kr = ks * 8 + (lane & 3);
            unsigned a[4][4], bf[4][2];
#pragma unroll
            for (int mt = 0; mt < 4; mt++) {
                a[mt][0] = As[b][kr][mbase + mt * 16];
                a[mt][1] = As[b][kr][mbase + mt * 16 + 8];
                a[mt][2] = As[b][kr + 4][mbase + mt * 16];
                a[mt][3] = As[b][kr + 4][mbase + mt * 16 + 8];
            }
#pragma unroll
            for (int nt = 0; nt < 4; nt++) {
                bf[nt][0] = Bs[b][kr][nbase + nt * 8];
                bf[nt][1] = Bs[b][kr + 4][nbase + nt * 8];
            }
#pragma unroll
            for (int mt = 0; mt < 4; mt++)
#pragma unroll
                for (int nt = 0; nt < 4; nt++)
                    mma_tf32(acc[mt * 4 + nt], a[mt], bf[nt]);
        }
        if (t < 31) {
            const int nb = b ^ 1;
            float af[8] = {av0.x,av0.y,av0.z,av0.w,av1.x,av1.y,av1.z,av1.w};
#pragma unroll
            for (int i = 0; i < 8; i++) As[nb][ak0 + i][arow] = f2tf(af[i]);
            uint4 p0 = {f2tf(bv0.x),f2tf(bv0.y),f2tf(bv0.z),f2tf(bv0.w)};
            uint4 p1 = {f2tf(bv1.x),f2tf(bv1.y),f2tf(bv1.z),f2tf(bv1.w)};
            *reinterpret_cast<uint4*>(&Bs[nb][brow][bcol])     = p0;
            *reinterpret_cast<uint4*>(&Bs[nb][brow][bcol + 4]) = p1;
            __syncthreads();
        }
    }

    // epilogue: scatter into [s][win][head][tok][d]
#pragma unroll
    for (int mt = 0; mt < 4; mt++) {
#pragma unroll
        for (int half = 0; half < 2; half++) {
            int r = row0 + wm * 64 + mt * 16 + (lane >> 2) + half * 8;
            int win = r / NTOK, tok = r - win * NTOK;
#pragma unroll
            for (int nt = 0; nt < 4; nt++) {
                int c = col0 + wn * 32 + nt * 8 + (lane & 3) * 2;
                int s = c >> 9, head = (c >> 5) & 15, dd = c & 31;
                size_t oidx = (((size_t)s * NWIN + win) * HEADS + head) * (NTOK * DHEAD)
                            + (size_t)tok * DHEAD + dd;
                float2 bv2 = *reinterpret_cast<const float2*>(bias + c);
                float2 ov;
                ov.x = acc[mt * 4 + nt][half * 2]     + bv2.x;
                ov.y = acc[mt * 4 + nt][half * 2 + 1] + bv2.y;
                *reinterpret_cast<float2*>(&g_qkv[oidx]) = ov;
            }
        }
    }
}

// ---------------------------------------------------------------------------
// Kernel 2: windowed attention, one block per (window, head). 256 threads.
// ---------------------------------------------------------------------------
#define QS 36  // padded row stride for q/k/v in smem (float4-aligned)
__global__ __launch_bounds__(256) void attn_kernel(const float* __restrict__ table) {
    const int wh = blockIdx.x;
    const int win = wh >> 4;
    const int head = wh & 15;
    const int tid = threadIdx.x;

    __shared__ float qs[NTOK * QS];
    __shared__ float ks[NTOK * QS];
    __shared__ float vs[NTOK * QS];
    __shared__ float S[NTOK * NTOK];
    __shared__ float tbl[169];
    __shared__ int reg[NTOK];

    const size_t SOFF = (size_t)NWIN * HEADS * NTOK * DHEAD;
    const size_t base = ((size_t)win * HEADS + head) * (NTOK * DHEAD);

    for (int idx = tid; idx < 392; idx += 256) {
        int t = idx >> 3, dd = (idx & 7) * 4;
        *reinterpret_cast<float4*>(&qs[t * QS + dd]) =
            *reinterpret_cast<const float4*>(&g_qkv[base + t * 32 + dd]);
        *reinterpret_cast<float4*>(&ks[t * QS + dd]) =
            *reinterpret_cast<const float4*>(&g_qkv[SOFF + base + t * 32 + dd]);
        *reinterpret_cast<float4*>(&vs[t * QS + dd]) =
            *reinterpret_cast<const float4*>(&g_qkv[2 * SOFF + base + t * 32 + dd]);
    }
    if (tid < 169) tbl[tid] = table[tid * HEADS + head];
    if (tid >= 192 && tid < 192 + NTOK) {
        int t = tid - 192;
        int wy = (win >> 3) & 7, wx = win & 7;
        int ty = t / WSZ, tx = t - ty * WSZ;
        int hs = wy * WSZ + ty, ws = wx * WSZ + tx;
        int rh = (hs < 49) ? 0 : ((hs < 53) ? 1 : 2);
        int rw = (ws < 49) ? 0 : ((ws < 53) ? 1 : 2);
        reg[t] = rh * 3 + rw;
    }
    __syncthreads();

    const float scale = 0.17677669529663687f;

    if (tid < 196) {
        const int i = tid >> 2, jq = tid & 3;
        const int j0 = jq * 13, j1 = (jq == 3) ? 49 : j0 + 13;
        float4 qv[8];
#pragma unroll
        for (int wv = 0; wv < 8; wv++)
            qv[wv] = *reinterpret_cast<const float4*>(&qs[i * QS + wv * 4]);
        const int iy = i / WSZ, ix = i - iy * WSZ;
        const int ri = reg[i];
        for (int j = j0; j < j1; j++) {
            float d = 0.0f;
#pragma unroll
            for (int wv = 0; wv < 8; wv++) {
                float4 kv = *reinterpret_cast<const float4*>(&ks[j * QS + wv * 4]);
                d += qv[wv].x * kv.x + qv[wv].y * kv.y + qv[wv].z * kv.z + qv[wv].w * kv.w;
            }
            int jy = j / WSZ, jx = j - jy * WSZ;
            int ridx = (iy - jy + 6) * 13 + (ix - jx + 6);
            float m = (ri != reg[j]) ? -100.0f : 0.0f;
            S[i * NTOK + j] = d * scale + tbl[ridx] + m;
        }
    }
    __syncthreads();

    if (tid < NTOK) {
        float mx = -1e30f;
#pragma unroll
        for (int j = 0; j < NTOK; j++) mx = fmaxf(mx, S[tid * NTOK + j]);
        float sum = 0.0f;
#pragma unroll
        for (int j = 0; j < NTOK; j++) {
            float e = __expf(S[tid * NTOK + j] - mx);
            S[tid * NTOK + j] = e;
            sum += e;
        }
        float inv = 1.0f / sum;
#pragma unroll
        for (int j = 0; j < NTOK; j++) S[tid * NTOK + j] *= inv;
    }
    __syncthreads();

    for (int idx = tid; idx < 392; idx += 256) {
        int i = idx >> 3, dq = (idx & 7) * 4;
        float4 o = {0.0f, 0.0f, 0.0f, 0.0f};
        for (int j = 0; j < NTOK; j++) {
            float s = S[i * NTOK + j];
            float4 v = *reinterpret_cast<const float4*>(&vs[j * QS + dq]);
            o.x += s * v.x; o.y += s * v.y; o.z += s * v.z; o.w += s * v.w;
        }
        *reinterpret_cast<float4*>(
            &g_attnout[((size_t)win * NTOK + i) * CDIM + head * DHEAD + dq]) = o;
    }
}

// ---------------------------------------------------------------------------
// Kernel 3: proj GEMM (mma.sync tf32) + window reverse + bias + residual
// ---------------------------------------------------------------------------
__global__ __launch_bounds__(256, 1) void proj_gemm(const float* __restrict__ x,
                                                    const float* __restrict__ w,
                                                    const float* __restrict__ bias,
                                                    float* __restrict__ out) {
    __shared__ unsigned As[2][16][SMS];
    __shared__ unsigned Bs[2][16][SMS];

    const int tid  = threadIdx.x;
    const int row0 = blockIdx.y * 128;
    const int col0 = blockIdx.x * 128;
    const int lane = tid & 31, wid = tid >> 5;
    const int wm = wid >> 2, wn = wid & 3;

    float acc[16][4];
#pragma unroll
    for (int i = 0; i < 16; i++)
#pragma unroll
        for (int j = 0; j < 4; j++) acc[i][j] = 0.0f;

    const int arow = tid & 127, ak0 = (tid >> 7) * 8;
    const int brow = tid >> 4,  bcol = (tid & 15) * 8;

    float4 av0 = *reinterpret_cast<const float4*>(g_attnout + (size_t)(row0 + arow) * CDIM + ak0);
    float4 av1 = *reinterpret_cast<const float4*>(g_attnout + (size_t)(row0 + arow) * CDIM + ak0 + 4);
    float4 bv0 = *reinterpret_cast<const float4*>(w + (size_t)brow * CDIM + col0 + bcol);
    float4 bv1 = *reinterpret_cast<const float4*>(w + (size_t)brow * CDIM + col0 + bcol + 4);
    {
        float af[8] = {av0.x,av0.y,av0.z,av0.w,av1.x,av1.y,av1.z,av1.w};
#pragma unroll
        for (int i = 0; i < 8; i++) As[0][ak0 + i][arow] = f2tf(af[i]);
        uint4 p0 = {f2tf(bv0.x),f2tf(bv0.y),f2tf(bv0.z),f2tf(bv0.w)};
        uint4 p1 = {f2tf(bv1.x),f2tf(bv1.y),f2tf(bv1.z),f2tf(bv1.w)};
        *reinterpret_cast<uint4*>(&Bs[0][brow][bcol])     = p0;
        *reinterpret_cast<uint4*>(&Bs[0][brow][bcol + 4]) = p1;
    }
    __syncthreads();

    const int mbase = wm * 64 + (lane >> 2);
    const int nbase = wn * 32 + (lane >> 2);

#pragma unroll 1
    for (int t = 0; t < 32; t++) {
        const int b = t & 1;
        if (t < 31) {
            const int kt = (t + 1) * 16;
            av0 = *reinterpret_cast<const float4*>(g_attnout + (size_t)(row0 + arow) * CDIM + kt + ak0);
            av1 = *reinterpret_cast<const float4*>(g_attnout + (size_t)(row0 + arow) * CDIM + kt + ak0 + 4);
            bv0 = *reinterpret_cast<const float4*>(w + (size_t)(kt + brow) * CDIM + col0 + bcol);
            bv1 = *reinterpret_cast<const float4*>(w + (size_t)(kt + brow) * CDIM + col0 + bcol + 4);
        }
#pragma unroll
        for (int ks = 0; ks < 2; ks++) {
            const int kr = ks * 8 + (lane & 3);
            unsigned a[4][4], bf[4][2];
#pragma unroll
            for (int mt = 0; mt < 4; mt++) {
                a[mt][0] = As[b][kr][mbase + mt * 16];
                a[mt][1] = As[b][kr][mbase + mt * 16 + 8];
                a[mt][2] = As[b][kr + 4][mbase + mt * 16];
                a[mt][3] = As[b][kr + 4][mbase + mt * 16 + 8];
            }
#pragma unroll
            for (int nt = 0; nt < 4; nt++) {
                bf[nt][0] = Bs[b][kr][nbase + nt * 8];
                bf[nt][1] = Bs[b][kr + 4][nbase + nt * 8];
            }
#pragma unroll
            for (int mt = 0; mt < 4; mt++)
#pragma unroll
                for (int nt = 0; nt < 4; nt++)
                    mma_tf32(acc[mt * 4 + nt], a[mt], bf[nt]);
        }
        if (t < 31) {
            const int nb = b ^ 1;
            float af[8] = {av0.x,av0.y,av0.z,av0.w,av1.x,av1.y,av1.z,av1.w};
#pragma unroll
            for (int i = 0; i < 8; i++) As[nb][ak0 + i][arow] = f2tf(af[i]);
            uint4 p0 = {f2tf(bv0.x),f2tf(bv0.y),f2tf(bv0.z),f2tf(bv0.w)};
            uint4 p1 = {f2tf(bv1.x),f2tf(bv1.y),f2tf(bv1.z),f2tf(bv1.w)};
            *reinterpret_cast<uint4*>(&Bs[nb][brow][bcol])     = p0;
            *reinterpret_cast<uint4*>(&Bs[nb][brow][bcol + 4]) = p1;
            __syncthreads();
        }
    }

#pragma unroll
    for (int mt = 0; mt < 4; mt++) {
#pragma unroll
        for (int half = 0; half < 2; half++) {
            int r = row0 + wm * 64 + mt * 16 + (lane >> 2) + half * 8;
            size_t pix = (size_t)row_to_pixel(r) * CDIM;
#pragma unroll
            for (int nt = 0; nt < 4; nt++) {
                int c = col0 + wn * 32 + nt * 8 + (lane & 3) * 2;
                float2 bv2 = *reinterpret_cast<const float2*>(bias + c);
                float2 xv  = *reinterpret_cast<const float2*>(x + pix + c);
                float2 ov;
                ov.x = xv.x + acc[mt * 4 + nt][half * 2]     + bv2.x;
                ov.y = xv.y + acc[mt * 4 + nt][half * 2 + 1] + bv2.y;
                *reinterpret_cast<float2*>(&out[pix + c]) = ov;
            }
        }
    }
}

extern "C" void kernel_launch(void* const* d_in, const int* in_sizes, int n_in,
                              void* d_out, int out_size) {
    const float* x      = (const float*)d_in[0];
    const float* qkv_w  = (const float*)d_in[1];
    const float* qkv_b  = (const float*)d_in[2];
    const float* proj_w = (const float*)d_in[3];
    const float* proj_b = (const float*)d_in[4];
    const float* table  = (const float*)d_in[5];
    float* out = (float*)d_out;

    dim3 g1(1536 / 128, MROWS / 128);
    qkv_gemm<<<g1, 256>>>(x, qkv_w, qkv_b);

    attn_kernel<<<NWIN * HEADS, 256>>>(table);

    dim3 g3(CDIM / 128, MROWS / 128);
    proj_gemm<<<g3, 256>>>(x, proj_w, proj_b, out);
}

// round 6
// speedup vs baseline: 4.0502x; 1.5072x over previous
#include <cuda_runtime.h>
#include <cuda_bf16.h>
#include <cstdint>

#define WSZ 7
#define SHIFT 3
#define HEADS 16
#define NTOK 49
#define CDIM 512
#define DHEAD 32
#define HH 56
#define NWIN 1024
#define MROWS (NWIN*NTOK)  // 50176

__device__ float g_qkv[(size_t)3*NWIN*HEADS*NTOK*DHEAD];
__device__ float g_attnout[(size_t)MROWS*CDIM];

__device__ __forceinline__ int row_to_pixel(int r) {
    int win = r / NTOK, t = r - win * NTOK;
    int b  = win >> 6;
    int wy = (win >> 3) & 7;
    int wx = win & 7;
    int ty = t / WSZ, tx = t - ty * WSZ;
    int hs = wy * WSZ + ty;
    int ws = wx * WSZ + tx;
    int h = hs + SHIFT; if (h >= HH) h -= HH;
    int w = ws + SHIFT; if (w >= HH) w -= HH;
    return (b * HH + h) * HH + w;
}

__device__ __forceinline__ unsigned pkbf(float lo, float hi) {
    unsigned r; asm("cvt.rn.bf16x2.f32 %0, %1, %2;" : "=r"(r) : "f"(hi), "f"(lo)); return r;
}
__device__ __forceinline__ unsigned s2u(const void* p) {
    return (unsigned)__cvta_generic_to_shared(p);
}
__device__ __forceinline__ void ldsm4(unsigned* r, unsigned a) {
    asm volatile("ldmatrix.sync.aligned.m8n8.x4.shared.b16 {%0,%1,%2,%3}, [%4];"
                 : "=r"(r[0]), "=r"(r[1]), "=r"(r[2]), "=r"(r[3]) : "r"(a));
}
__device__ __forceinline__ void ldsm4t(unsigned* r, unsigned a) {
    asm volatile("ldmatrix.sync.aligned.m8n8.x4.trans.shared.b16 {%0,%1,%2,%3}, [%4];"
                 : "=r"(r[0]), "=r"(r[1]), "=r"(r[2]), "=r"(r[3]) : "r"(a));
}
__device__ __forceinline__ void mma_bf16(float* d, const unsigned* a, const unsigned* b) {
    asm volatile(
        "mma.sync.aligned.m16n8k16.row.col.f32.bf16.bf16.f32 "
        "{%0,%1,%2,%3}, {%4,%5,%6,%7}, {%8,%9}, {%0,%1,%2,%3};"
        : "+f"(d[0]), "+f"(d[1]), "+f"(d[2]), "+f"(d[3])
        : "r"(a[0]), "r"(a[1]), "r"(a[2]), "r"(a[3]), "r"(b[0]), "r"(b[1]));
}

#define ASTR 40    // A smem row stride (bf16): 80B -> conflict-free LDSM
#define BSTR 136   // B smem row stride (bf16): 272B -> conflict-free LDSM

// ---------------------------------------------------------------------------
// Kernel 1: QKV GEMM, bf16 mma.sync + ldmatrix. 128x128x32 tile, 256 thr.
// ---------------------------------------------------------------------------
__global__ __launch_bounds__(256, 1) void qkv_gemm(const float* __restrict__ x,
                                                   const float* __restrict__ w,
                                                   const float* __restrict__ bias) {
    __shared__ __align__(16) unsigned short As[2][128][ASTR];
    __shared__ __align__(16) unsigned short Bs[2][32][BSTR];
    __shared__ int rowoff[128];

    const int tid  = threadIdx.x;
    const int row0 = blockIdx.y * 128;
    const int col0 = blockIdx.x * 128;
    const int lane = tid & 31, wid = tid >> 5;
    const int wm = wid >> 2, wn = wid & 3;

    if (tid < 128) rowoff[tid] = row_to_pixel(row0 + tid) * CDIM;

    float acc[16][4];
#pragma unroll
    for (int i = 0; i < 16; i++)
#pragma unroll
        for (int j = 0; j < 4; j++) acc[i][j] = 0.0f;

    const int ar = tid >> 1, akc = (tid & 1) * 16;       // A: row, k-chunk
    const int bkr = tid >> 3, bnc = (tid & 7) * 16;      // B: k-row, n-chunk

    __syncthreads();

    // prologue: tile 0
    {
        const float* ap = x + rowoff[ar] + akc;
        float4 a0 = *reinterpret_cast<const float4*>(ap);
        float4 a1 = *reinterpret_cast<const float4*>(ap + 4);
        float4 a2 = *reinterpret_cast<const float4*>(ap + 8);
        float4 a3 = *reinterpret_cast<const float4*>(ap + 12);
        const float* bp = w + (size_t)bkr * 1536 + col0 + bnc;
        float4 b0 = *reinterpret_cast<const float4*>(bp);
        float4 b1 = *reinterpret_cast<const float4*>(bp + 4);
        float4 b2 = *reinterpret_cast<const float4*>(bp + 8);
        float4 b3 = *reinterpret_cast<const float4*>(bp + 12);
        uint4 pa0 = {pkbf(a0.x,a0.y), pkbf(a0.z,a0.w), pkbf(a1.x,a1.y), pkbf(a1.z,a1.w)};
        uint4 pa1 = {pkbf(a2.x,a2.y), pkbf(a2.z,a2.w), pkbf(a3.x,a3.y), pkbf(a3.z,a3.w)};
        *reinterpret_cast<uint4*>(&As[0][ar][akc])     = pa0;
        *reinterpret_cast<uint4*>(&As[0][ar][akc + 8]) = pa1;
        uint4 pb0 = {pkbf(b0.x,b0.y), pkbf(b0.z,b0.w), pkbf(b1.x,b1.y), pkbf(b1.z,b1.w)};
        uint4 pb1 = {pkbf(b2.x,b2.y), pkbf(b2.z,b2.w), pkbf(b3.x,b3.y), pkbf(b3.z,b3.w)};
        *reinterpret_cast<uint4*>(&Bs[0][bkr][bnc])     = pb0;
        *reinterpret_cast<uint4*>(&Bs[0][bkr][bnc + 8]) = pb1;
    }
    __syncthreads();

    // per-thread ldmatrix base offsets
    const int la_row = wm * 64 + (lane & 15);
    const int la_col = (lane >> 4) * 8;
    const int lb_row = lane & 15;
    const int lb_col = wn * 32 + (lane >> 4) * 8;

    float4 a0, a1, a2, a3, b0, b1, b2, b3;

#pragma unroll 1
    for (int t = 0; t < 16; t++) {
        const int buf = t & 1;
        if (t < 15) {
            const int kt = (t + 1) * 32;
            const float* ap = x + rowoff[ar] + kt + akc;
            a0 = *reinterpret_cast<const float4*>(ap);
            a1 = *reinterpret_cast<const float4*>(ap + 4);
            a2 = *reinterpret_cast<const float4*>(ap + 8);
            a3 = *reinterpret_cast<const float4*>(ap + 12);
            const float* bp = w + (size_t)(kt + bkr) * 1536 + col0 + bnc;
            b0 = *reinterpret_cast<const float4*>(bp);
            b1 = *reinterpret_cast<const float4*>(bp + 4);
            b2 = *reinterpret_cast<const float4*>(bp + 8);
            b3 = *reinterpret_cast<const float4*>(bp + 12);
        }
#pragma unroll
        for (int ks = 0; ks < 2; ks++) {
            unsigned afr[4][4], bfr[2][4];
#pragma unroll
            for (int mt = 0; mt < 4; mt++)
                ldsm4(afr[mt], s2u(&As[buf][la_row + mt * 16][ks * 16 + la_col]));
#pragma unroll
            for (int n2 = 0; n2 < 2; n2++)
                ldsm4t(bfr[n2], s2u(&Bs[buf][ks * 16 + lb_row][lb_col + n2 * 16]));
#pragma unroll
            for (int mt = 0; mt < 4; mt++)
#pragma unroll
                for (int nt = 0; nt < 4; nt++)
                    mma_bf16(acc[mt * 4 + nt], afr[mt], &bfr[nt >> 1][(nt & 1) * 2]);
        }
        if (t < 15) {
            const int nb = buf ^ 1;
            uint4 pa0 = {pkbf(a0.x,a0.y), pkbf(a0.z,a0.w), pkbf(a1.x,a1.y), pkbf(a1.z,a1.w)};
            uint4 pa1 = {pkbf(a2.x,a2.y), pkbf(a2.z,a2.w), pkbf(a3.x,a3.y), pkbf(a3.z,a3.w)};
            *reinterpret_cast<uint4*>(&As[nb][ar][akc])     = pa0;
            *reinterpret_cast<uint4*>(&As[nb][ar][akc + 8]) = pa1;
            uint4 pb0 = {pkbf(b0.x,b0.y), pkbf(b0.z,b0.w), pkbf(b1.x,b1.y), pkbf(b1.z,b1.w)};
            uint4 pb1 = {pkbf(b2.x,b2.y), pkbf(b2.z,b2.w), pkbf(b3.x,b3.y), pkbf(b3.z,b3.w)};
            *reinterpret_cast<uint4*>(&Bs[nb][bkr][bnc])     = pb0;
            *reinterpret_cast<uint4*>(&Bs[nb][bkr][bnc + 8]) = pb1;
            __syncthreads();
        }
    }

    // epilogue: scatter into [s][win][head][tok][d]
#pragma unroll
    for (int mt = 0; mt < 4; mt++) {
#pragma unroll
        for (int half = 0; half < 2; half++) {
            int r = row0 + wm * 64 + mt * 16 + (lane >> 2) + half * 8;
            int win = r / NTOK, tok = r - win * NTOK;
#pragma unroll
            for (int nt = 0; nt < 4; nt++) {
                int c = col0 + wn * 32 + nt * 8 + (lane & 3) * 2;
                int s = c >> 9, head = (c >> 5) & 15, dd = c & 31;
                size_t oidx = (((size_t)s * NWIN + win) * HEADS + head) * (NTOK * DHEAD)
                            + (size_t)tok * DHEAD + dd;
                float2 bv2 = *reinterpret_cast<const float2*>(bias + c);
                float2 ov;
                ov.x = acc[mt * 4 + nt][half * 2]     + bv2.x;
                ov.y = acc[mt * 4 + nt][half * 2 + 1] + bv2.y;
                *reinterpret_cast<float2*>(&g_qkv[oidx]) = ov;
            }
        }
    }
}

// ---------------------------------------------------------------------------
// Kernel 2: windowed attention, one block per (window, head). 256 threads.
// ---------------------------------------------------------------------------
#define QS 36
__global__ __launch_bounds__(256) void attn_kernel(const float* __restrict__ table) {
    const int wh = blockIdx.x;
    const int win = wh >> 4;
    const int head = wh & 15;
    const int tid = threadIdx.x;

    __shared__ float qs[NTOK * QS];
    __shared__ float ks[NTOK * QS];
    __shared__ float vs[NTOK * QS];
    __shared__ float S[NTOK * NTOK];
    __shared__ float tbl[169];
    __shared__ int reg[NTOK];

    const size_t SOFF = (size_t)NWIN * HEADS * NTOK * DHEAD;
    const size_t base = ((size_t)win * HEADS + head) * (NTOK * DHEAD);

    for (int idx = tid; idx < 392; idx += 256) {
        int t = idx >> 3, dd = (idx & 7) * 4;
        *reinterpret_cast<float4*>(&qs[t * QS + dd]) =
            *reinterpret_cast<const float4*>(&g_qkv[base + t * 32 + dd]);
        *reinterpret_cast<float4*>(&ks[t * QS + dd]) =
            *reinterpret_cast<const float4*>(&g_qkv[SOFF + base + t * 32 + dd]);
        *reinterpret_cast<float4*>(&vs[t * QS + dd]) =
            *reinterpret_cast<const float4*>(&g_qkv[2 * SOFF + base + t * 32 + dd]);
    }
    if (tid < 169) tbl[tid] = table[tid * HEADS + head];
    if (tid >= 192 && tid < 192 + NTOK) {
        int t = tid - 192;
        int wy = (win >> 3) & 7, wx = win & 7;
        int ty = t / WSZ, tx = t - ty * WSZ;
        int hs = wy * WSZ + ty, ws = wx * WSZ + tx;
        int rh = (hs < 49) ? 0 : ((hs < 53) ? 1 : 2);
        int rw = (ws < 49) ? 0 : ((ws < 53) ? 1 : 2);
        reg[t] = rh * 3 + rw;
    }
    __syncthreads();

    const float scale = 0.17677669529663687f;

    if (tid < 196) {
        const int i = tid >> 2, jq = tid & 3;
        const int j0 = jq * 13, j1 = (jq == 3) ? 49 : j0 + 13;
        float4 qv[8];
#pragma unroll
        for (int wv = 0; wv < 8; wv++)
            qv[wv] = *reinterpret_cast<const float4*>(&qs[i * QS + wv * 4]);
        const int iy = i / WSZ, ix = i - iy * WSZ;
        const int ri = reg[i];
        for (int j = j0; j < j1; j++) {
            float d = 0.0f;
#pragma unroll
            for (int wv = 0; wv < 8; wv++) {
                float4 kv = *reinterpret_cast<const float4*>(&ks[j * QS + wv * 4]);
                d += qv[wv].x * kv.x + qv[wv].y * kv.y + qv[wv].z * kv.z + qv[wv].w * kv.w;
            }
            int jy = j / WSZ, jx = j - jy * WSZ;
            int ridx = (iy - jy + 6) * 13 + (ix - jx + 6);
            float m = (ri != reg[j]) ? -100.0f : 0.0f;
            S[i * NTOK + j] = d * scale + tbl[ridx] + m;
        }
    }
    __syncthreads();

    if (tid < NTOK) {
        float mx = -1e30f;
#pragma unroll
        for (int j = 0; j < NTOK; j++) mx = fmaxf(mx, S[tid * NTOK + j]);
        float sum = 0.0f;
#pragma unroll
        for (int j = 0; j < NTOK; j++) {
            float e = __expf(S[tid * NTOK + j] - mx);
            S[tid * NTOK + j] = e;
            sum += e;
        }
        float inv = 1.0f / sum;
#pragma unroll
        for (int j = 0; j < NTOK; j++) S[tid * NTOK + j] *= inv;
    }
    __syncthreads();

    for (int idx = tid; idx < 392; idx += 256) {
        int i = idx >> 3, dq = (idx & 7) * 4;
        float4 o = {0.0f, 0.0f, 0.0f, 0.0f};
        for (int j = 0; j < NTOK; j++) {
            float s = S[i * NTOK + j];
            float4 v = *reinterpret_cast<const float4*>(&vs[j * QS + dq]);
            o.x += s * v.x; o.y += s * v.y; o.z += s * v.z; o.w += s * v.w;
        }
        *reinterpret_cast<float4*>(
            &g_attnout[((size_t)win * NTOK + i) * CDIM + head * DHEAD + dq]) = o;
    }
}

// ---------------------------------------------------------------------------
// Kernel 3: proj GEMM bf16 mma.sync + window reverse + bias + residual
// ---------------------------------------------------------------------------
__global__ __launch_bounds__(256, 1) void proj_gemm(const float* __restrict__ x,
                                                    const float* __restrict__ w,
                                                    const float* __restrict__ bias,
                                                    float* __restrict__ out) {
    __shared__ __align__(16) unsigned short As[2][128][ASTR];
    __shared__ __align__(16) unsigned short Bs[2][32][BSTR];

    const int tid  = threadIdx.x;
    const int row0 = blockIdx.y * 128;
    const int col0 = blockIdx.x * 128;
    const int lane = tid & 31, wid = tid >> 5;
    const int wm = wid >> 2, wn = wid & 3;

    float acc[16][4];
#pragma unroll
    for (int i = 0; i < 16; i++)
#pragma unroll
        for (int j = 0; j < 4; j++) acc[i][j] = 0.0f;

    const int ar = tid >> 1, akc = (tid & 1) * 16;
    const int bkr = tid >> 3, bnc = (tid & 7) * 16;

    {
        const float* ap = g_attnout + (size_t)(row0 + ar) * CDIM + akc;
        float4 a0 = *reinterpret_cast<const float4*>(ap);
        float4 a1 = *reinterpret_cast<const float4*>(ap + 4);
        float4 a2 = *reinterpret_cast<const float4*>(ap + 8);
        float4 a3 = *reinterpret_cast<const float4*>(ap + 12);
        const float* bp = w + (size_t)bkr * CDIM + col0 + bnc;
        float4 b0 = *reinterpret_cast<const float4*>(bp);
        float4 b1 = *reinterpret_cast<const float4*>(bp + 4);
        float4 b2 = *reinterpret_cast<const float4*>(bp + 8);
        float4 b3 = *reinterpret_cast<const float4*>(bp + 12);
        uint4 pa0 = {pkbf(a0.x,a0.y), pkbf(a0.z,a0.w), pkbf(a1.x,a1.y), pkbf(a1.z,a1.w)};
        uint4 pa1 = {pkbf(a2.x,a2.y), pkbf(a2.z,a2.w), pkbf(a3.x,a3.y), pkbf(a3.z,a3.w)};
        *reinterpret_cast<uint4*>(&As[0][ar][akc])     = pa0;
        *reinterpret_cast<uint4*>(&As[0][ar][akc + 8]) = pa1;
        uint4 pb0 = {pkbf(b0.x,b0.y), pkbf(b0.z,b0.w), pkbf(b1.x,b1.y), pkbf(b1.z,b1.w)};
        uint4 pb1 = {pkbf(b2.x,b2.y), pkbf(b2.z,b2.w), pkbf(b3.x,b3.y), pkbf(b3.z,b3.w)};
        *reinterpret_cast<uint4*>(&Bs[0][bkr][bnc])     = pb0;
        *reinterpret_cast<uint4*>(&Bs[0][bkr][bnc + 8]) = pb1;
    }
    __syncthreads();

    const int la_row = wm * 64 + (lane & 15);
    const int la_col = (lane >> 4) * 8;
    const int lb_row = lane & 15;
    const int lb_col = wn * 32 + (lane >> 4) * 8;

    float4 a0, a1, a2, a3, b0, b1, b2, b3;

#pragma unroll 1
    for (int t = 0; t < 16; t++) {
        const int buf = t & 1;
        if (t < 15) {
            const int kt = (t + 1) * 32;
            const float* ap = g_attnout + (size_t)(row0 + ar) * CDIM + kt + akc;
            a0 = *reinterpret_cast<const float4*>(ap);
            a1 = *reinterpret_cast<const float4*>(ap + 4);
            a2 = *reinterpret_cast<const float4*>(ap + 8);
            a3 = *reinterpret_cast<const float4*>(ap + 12);
            const float* bp = w + (size_t)(kt + bkr) * CDIM + col0 + bnc;
            b0 = *reinterpret_cast<const float4*>(bp);
            b1 = *reinterpret_cast<const float4*>(bp + 4);
            b2 = *reinterpret_cast<const float4*>(bp + 8);
            b3 = *reinterpret_cast<const float4*>(bp + 12);
        }
#pragma unroll
        for (int ks = 0; ks < 2; ks++) {
            unsigned afr[4][4], bfr[2][4];
#pragma unroll
            for (int mt = 0; mt < 4; mt++)
                ldsm4(afr[mt], s2u(&As[buf][la_row + mt * 16][ks * 16 + la_col]));
#pragma unroll
            for (int n2 = 0; n2 < 2; n2++)
                ldsm4t(bfr[n2], s2u(&Bs[buf][ks * 16 + lb_row][lb_col + n2 * 16]));
#pragma unroll
            for (int mt = 0; mt < 4; mt++)
#pragma unroll
                for (int nt = 0; nt < 4; nt++)
                    mma_bf16(acc[mt * 4 + nt], afr[mt], &bfr[nt >> 1][(nt & 1) * 2]);
        }
        if (t < 15) {
            const int nb = buf ^ 1;
            uint4 pa0 = {pkbf(a0.x,a0.y), pkbf(a0.z,a0.w), pkbf(a1.x,a1.y), pkbf(a1.z,a1.w)};
            uint4 pa1 = {pkbf(a2.x,a2.y), pkbf(a2.z,a2.w), pkbf(a3.x,a3.y), pkbf(a3.z,a3.w)};
            *reinterpret_cast<uint4*>(&As[nb][ar][akc])     = pa0;
            *reinterpret_cast<uint4*>(&As[nb][ar][akc + 8]) = pa1;
            uint4 pb0 = {pkbf(b0.x,b0.y), pkbf(b0.z,b0.w), pkbf(b1.x,b1.y), pkbf(b1.z,b1.w)};
            uint4 pb1 = {pkbf(b2.x,b2.y), pkbf(b2.z,b2.w), pkbf(b3.x,b3.y), pkbf(b3.z,b3.w)};
            *reinterpret_cast<uint4*>(&Bs[nb][bkr][bnc])     = pb0;
            *reinterpret_cast<uint4*>(&Bs[nb][bkr][bnc + 8]) = pb1;
            __syncthreads();
        }
    }

#pragma unroll
    for (int mt = 0; mt < 4; mt++) {
#pragma unroll
        for (int half = 0; half < 2; half++) {
            int r = row0 + wm * 64 + mt * 16 + (lane >> 2) + half * 8;
            size_t pix = (size_t)row_to_pixel(r) * CDIM;
#pragma unroll
            for (int nt = 0; nt < 4; nt++) {
                int c = col0 + wn * 32 + nt * 8 + (lane & 3) * 2;
                float2 bv2 = *reinterpret_cast<const float2*>(bias + c);
                float2 xv  = *reinterpret_cast<const float2*>(x + pix + c);
                float2 ov;
                ov.x = xv.x + acc[mt * 4 + nt][half * 2]     + bv2.x;
                ov.y = xv.y + acc[mt * 4 + nt][half * 2 + 1] + bv2.y;
                *reinterpret_cast<float2*>(&out[pix + c]) = ov;
            }
        }
    }
}

extern "C" void kernel_launch(void* const* d_in, const int* in_sizes, int n_in,
                              void* d_out, int out_size) {
    const float* x      = (const float*)d_in[0];
    const float* qkv_w  = (const float*)d_in[1];
    const float* qkv_b  = (const float*)d_in[2];
    const float* proj_w = (const float*)d_in[3];
    const float* proj_b = (const float*)d_in[4];
    const float* table  = (const float*)d_in[5];
    float* out = (float*)d_out;

    dim3 g1(1536 / 128, MROWS / 128);
    qkv_gemm<<<g1, 256>>>(x, qkv_w, qkv_b);

    attn_kernel<<<NWIN * HEADS, 256>>>(table);

    dim3 g3(CDIM / 128, MROWS / 128);
    proj_gemm<<<g3, 256>>>(x, proj_w, proj_b, out);
}

// round 9
// speedup vs baseline: 4.6683x; 1.1526x over previous
#include <cuda_runtime.h>
#include <cuda_bf16.h>
#include <cstdint>

#define WSZ 7
#define SHIFT 3
#define HEADS 16
#define NTOK 49
#define CDIM 512
#define DHEAD 32
#define HH 56
#define NWIN 1024
#define MROWS (NWIN*NTOK)   // 50176
#define NPIX  MROWS

typedef unsigned long long ull;

// bf16 pair-packed scratch
__device__ unsigned g_xbf[(size_t)NPIX*256];              // x bf16 [pix][512]
__device__ unsigned g_wqkv_t[1536*256];                   // qkv_w^T bf16 [n][k]
__device__ unsigned g_wproj_t[512*256];                   // proj_w^T bf16 [n][k]
__device__ unsigned g_qkvb[(size_t)3*NWIN*HEADS*NTOK*16]; // qkv bf16 [s][win][head][tok][32]
__device__ unsigned g_attnb[(size_t)MROWS*256];           // attn out bf16 [row][512]

__device__ __forceinline__ int row_to_pixel(int r) {
    int win = r / NTOK, t = r - win * NTOK;
    int b  = win >> 6;
    int wy = (win >> 3) & 7;
    int wx = win & 7;
    int ty = t / WSZ, tx = t - ty * WSZ;
    int hs = wy * WSZ + ty;
    int ws = wx * WSZ + tx;
    int h = hs + SHIFT; if (h >= HH) h -= HH;
    int w = ws + SHIFT; if (w >= HH) w -= HH;
    return (b * HH + h) * HH + w;
}

__device__ __forceinline__ unsigned pkbf(float lo, float hi) {
    unsigned r; asm("cvt.rn.bf16x2.f32 %0, %1, %2;" : "=r"(r) : "f"(hi), "f"(lo)); return r;
}
__device__ __forceinline__ ull pack2(float x) {
    ull r; asm("mov.b64 %0, {%1, %1};" : "=l"(r) : "f"(x)); return r;
}
__device__ __forceinline__ void fma2(ull& d, ull a, ull b) {
    asm("fma.rn.f32x2 %0, %1, %2, %3;" : "=l"(d) : "l"(a), "l"(b), "l"(d));
}
__device__ __forceinline__ float2 unpack2(ull v) {
    float2 f; asm("mov.b64 {%0, %1}, %2;" : "=f"(f.x), "=f"(f.y) : "l"(v)); return f;
}
__device__ __forceinline__ void expand8(float* dst, uint4 v) {
    unsigned a[4] = {v.x, v.y, v.z, v.w};
#pragma unroll
    for (int i = 0; i < 4; i++) {
        dst[2*i]   = __uint_as_float(a[i] << 16);
        dst[2*i+1] = __uint_as_float(a[i] & 0xffff0000u);
    }
}
__device__ __forceinline__ unsigned s2u(const void* p) {
    return (unsigned)__cvta_generic_to_shared(p);
}
__device__ __forceinline__ void ldsm4(unsigned* r, unsigned a) {
    asm volatile("ldmatrix.sync.aligned.m8n8.x4.shared.b16 {%0,%1,%2,%3}, [%4];"
                 : "=r"(r[0]), "=r"(r[1]), "=r"(r[2]), "=r"(r[3]) : "r"(a));
}
__device__ __forceinline__ void mma_bf16(float* d, const unsigned* a, const unsigned* b) {
    asm volatile(
        "mma.sync.aligned.m16n8k16.row.col.f32.bf16.bf16.f32 "
        "{%0,%1,%2,%3}, {%4,%5,%6,%7}, {%8,%9}, {%0,%1,%2,%3};"
        : "+f"(d[0]), "+f"(d[1]), "+f"(d[2]), "+f"(d[3])
        : "r"(a[0]), "r"(a[1]), "r"(a[2]), "r"(a[3]), "r"(b[0]), "r"(b[1]));
}
__device__ __forceinline__ void cp16(unsigned dst, const void* src) {
    asm volatile("cp.async.cg.shared.global [%0], [%1], 16;" :: "r"(dst), "l"(src) : "memory");
}
__device__ __forceinline__ void cp_commit() { asm volatile("cp.async.commit_group;" ::: "memory"); }
__device__ __forceinline__ void cp_wait0()  { asm volatile("cp.async.wait_group 0;" ::: "memory"); }

#define STR 40   // smem row stride (bf16) = 80B -> conflict-free LDSM

// ---------------------------------------------------------------------------
// Prepasses
// ---------------------------------------------------------------------------
__global__ void cvt_x_kernel(const float* __restrict__ x) {
    size_t i = (size_t)blockIdx.x * 256 + threadIdx.x;
    float4 v = *reinterpret_cast<const float4*>(x + i * 4);
    uint2 o = { pkbf(v.x, v.y), pkbf(v.z, v.w) };
    *reinterpret_cast<uint2*>(&g_xbf[i * 2]) = o;
}
__global__ void wtrans_kernel(const float* __restrict__ w, int ncols, int which) {
    int n = blockIdx.x, t = threadIdx.x;     // t = k-pair
    float a = w[(size_t)(2 * t)     * ncols + n];
    float b = w[(size_t)(2 * t + 1) * ncols + n];
    unsigned v = pkbf(a, b);
    if (which) g_wproj_t[n * 256 + t] = v; else g_wqkv_t[n * 256 + t] = v;
}

// ---------------------------------------------------------------------------
// bf16 GEMM core: 128x128x32 tiles, cp.async double-buffered, mma.sync.
// Shared by qkv and proj via templates on source/epilogue.
// ---------------------------------------------------------------------------
__global__ __launch_bounds__(256, 1) void qkv_gemm(const float* __restrict__ bias) {
    __shared__ __align__(16) unsigned short As[2][128][STR];
    __shared__ __align__(16) unsigned short Bs[2][128][STR];
    __shared__ int rowoff[128];

    const int tid = threadIdx.x;
    const int row0 = blockIdx.y * 128, col0 = blockIdx.x * 128;
    const int lane = tid & 31, wid = tid >> 5;
    const int wm = wid >> 2, wn = wid & 3;

    if (tid < 128) rowoff[tid] = row_to_pixel(row0 + tid) * 256;  // uints
    __syncthreads();

    float acc[16][4];
#pragma unroll
    for (int i = 0; i < 16; i++)
#pragma unroll
        for (int j = 0; j < 4; j++) acc[i][j] = 0.0f;

    const int srow = tid >> 1, sseg = (tid & 1) * 2;   // 2 segs of 16B each

    auto stage = [&](int buf, int kt) {
        const int k16 = kt * 16;   // uint offset of this k-tile
#pragma unroll
        for (int q = 0; q < 2; q++) {
            int seg = sseg + q;
            cp16(s2u(&As[buf][srow][seg * 8]), &g_xbf[(size_t)rowoff[srow] + k16 + seg * 4]);
            cp16(s2u(&Bs[buf][srow][seg * 8]), &g_wqkv_t[(size_t)(col0 + srow) * 256 + k16 + seg * 4]);
        }
    };

    stage(0, 0);
    cp_commit();

    const unsigned a_base = s2u(&As[0][0][0]);
    const unsigned b_base = s2u(&Bs[0][0][0]);
    const unsigned bufsz = 128 * STR * 2;
    const int a_row = wm * 64 + (lane & 15);
    const int a_colB = (lane >> 4) * 16;
    const int b_row = wn * 32 + ((lane >> 4) & 1) * 8 + (lane & 7);
    const int b_colB = ((lane >> 3) & 1) * 16;

#pragma unroll 1
    for (int t = 0; t < 16; t++) {
        const int buf = t & 1;
        cp_wait0();
        __syncthreads();
        if (t < 15) { stage(buf ^ 1, t + 1); cp_commit(); }
        const unsigned ab = a_base + buf * bufsz;
        const unsigned bb = b_base + buf * bufsz;
#pragma unroll
        for (int ks = 0; ks < 2; ks++) {
            unsigned afr[4][4], bfr[2][4];
#pragma unroll
            for (int mt = 0; mt < 4; mt++)
                ldsm4(afr[mt], ab + (unsigned)((a_row + mt * 16) * (STR * 2) + ks * 32 + a_colB));
#pragma unroll
            for (int n2 = 0; n2 < 2; n2++)
                ldsm4(bfr[n2], bb + (unsigned)((b_row + n2 * 16) * (STR * 2) + ks * 32 + b_colB));
#pragma unroll
            for (int mt = 0; mt < 4; mt++)
#pragma unroll
                for (int nt = 0; nt < 4; nt++)
                    mma_bf16(acc[mt * 4 + nt], afr[mt], &bfr[nt >> 1][(nt & 1) * 2]);
        }
        __syncthreads();
    }

    // epilogue: +bias, pack bf16, scatter into g_qkvb
#pragma unroll
    for (int mt = 0; mt < 4; mt++) {
#pragma unroll
        for (int half = 0; half < 2; half++) {
            int r = row0 + wm * 64 + mt * 16 + (lane >> 2) + half * 8;
            int win = r / NTOK, tok = r - win * NTOK;
#pragma unroll
            for (int nt = 0; nt < 4; nt++) {
                int c = col0 + wn * 32 + nt * 8 + (lane & 3) * 2;
                int s = c >> 9, head = (c >> 5) & 15, dd = c & 31;
                size_t ub = (((size_t)s * NWIN + win) * HEADS + head) * (NTOK * 16)
                          + (size_t)tok * 16 + (dd >> 1);
                float lo = acc[mt * 4 + nt][half * 2]     + bias[c];
                float hi = acc[mt * 4 + nt][half * 2 + 1] + bias[c + 1];
                g_qkvb[ub] = pkbf(lo, hi);
            }
        }
    }
}

// ---------------------------------------------------------------------------
// Kernel 2: windowed attention, bf16 IO, f32x2 math. Block per (win, head).
// ---------------------------------------------------------------------------
__global__ __launch_bounds__(256) void attn_kernel(const float* __restrict__ table) {
    const int wh = blockIdx.x;
    const int win = wh >> 4;
    const int head = wh & 15;
    const int tid = threadIdx.x;

    __shared__ float qs[NTOK * 36];
    __shared__ float ks_[NTOK * 36];
    __shared__ float vs[NTOK * 36];
    __shared__ float S[NTOK * NTOK];
    __shared__ float tbl[169];
    __shared__ int reg[NTOK];

    const size_t SOFF2 = (size_t)NWIN * HEADS * NTOK * 16;
    const size_t base2 = ((size_t)win * HEADS + head) * (NTOK * 16);

    if (tid < 196) {
        int t = tid >> 2, ub = (tid & 3) * 4, dd = (tid & 3) * 8;
        uint4 q4 = *reinterpret_cast<const uint4*>(&g_qkvb[base2 + t * 16 + ub]);
        uint4 k4 = *reinterpret_cast<const uint4*>(&g_qkvb[SOFF2 + base2 + t * 16 + ub]);
        uint4 v4 = *reinterpret_cast<const uint4*>(&g_qkvb[2 * SOFF2 + base2 + t * 16 + ub]);
        expand8(&qs[t * 36 + dd], q4);
        expand8(&ks_[t * 36 + dd], k4);
        expand8(&vs[t * 36 + dd], v4);
    }
    if (tid < 169) tbl[tid] = table[tid * HEADS + head];
    if (tid >= 200 && tid < 200 + NTOK) {
        int t = tid - 200;
        int wy = (win >> 3) & 7, wx = win & 7;
        int ty = t / WSZ, tx = t - ty * WSZ;
        int hs = wy * WSZ + ty, ws = wx * WSZ + tx;
        int rh = (hs < 49) ? 0 : ((hs < 53) ? 1 : 2);
        int rw = (ws < 49) ? 0 : ((ws < 53) ? 1 : 2);
        reg[t] = rh * 3 + rw;
    }
    __syncthreads();

    const float scale = 0.17677669529663687f;

    if (tid < 196) {
        const int i = tid >> 2, jq = tid & 3;
        const int j0 = jq * 13, j1 = (jq == 3) ? 49 : j0 + 13;
        ull qv[16];
#pragma unroll
        for (int p = 0; p < 16; p++)
            qv[p] = *reinterpret_cast<const ull*>(&qs[i * 36 + 2 * p]);
        const int iy = i / WSZ, ix = i - iy * WSZ;
        const int ri = reg[i];
        for (int j = j0; j < j1; j++) {
            ull a0 = 0ull, a1 = 0ull;
            const ull* kp = reinterpret_cast<const ull*>(&ks_[j * 36]);
#pragma unroll
            for (int p = 0; p < 16; p += 2) { fma2(a0, qv[p], kp[p]); fma2(a1, qv[p+1], kp[p+1]); }
            float2 f0 = unpack2(a0), f1 = unpack2(a1);
            float d = (f0.x + f0.y) + (f1.x + f1.y);
            int jy = j / WSZ, jx = j - jy * WSZ;
            int ridx = (iy - jy + 6) * 13 + (ix - jx + 6);
            float m = (ri != reg[j]) ? -100.0f : 0.0f;
            S[i * NTOK + j] = d * scale + tbl[ridx] + m;
        }
    }
    __syncthreads();

    if (tid < NTOK) {
        float mx = -1e30f;
#pragma unroll
        for (int j = 0; j < NTOK; j++) mx = fmaxf(mx, S[tid * NTOK + j]);
        float sum = 0.0f;
#pragma unroll
        for (int j = 0; j < NTOK; j++) {
            float e = __expf(S[tid * NTOK + j] - mx);
            S[tid * NTOK + j] = e;
            sum += e;
        }
        float inv = 1.0f / sum;
#pragma unroll
        for (int j = 0; j < NTOK; j++) S[tid * NTOK + j] *= inv;
    }
    __syncthreads();

    for (int idx = tid; idx < 392; idx += 256) {
        int i = idx >> 3, dq = (idx & 7) * 4;
        ull o0 = 0ull, o1 = 0ull;
        const float* sp = &S[i * NTOK];
        for (int j = 0; j < NTOK; j++) {
            ull sv = pack2(sp[j]);
            const ull* vp = reinterpret_cast<const ull*>(&vs[j * 36 + dq]);
            fma2(o0, sv, vp[0]);
            fma2(o1, sv, vp[1]);
        }
        float2 a = unpack2(o0), b = unpack2(o1);
        uint2 ov = { pkbf(a.x, a.y), pkbf(b.x, b.y) };
        *reinterpret_cast<uint2*>(&g_attnb[((size_t)win * NTOK + i) * 256 + head * 16 + (dq >> 1)]) = ov;
    }
}

// ---------------------------------------------------------------------------
// Kernel 3: proj GEMM + window reverse + bias + residual (f32 out)
// ---------------------------------------------------------------------------
__global__ __launch_bounds__(256, 1) void proj_gemm(const float* __restrict__ x,
                                                    const float* __restrict__ bias,
                                                    float* __restrict__ out) {
    __shared__ __align__(16) unsigned short As[2][128][STR];
    __shared__ __align__(16) unsigned short Bs[2][128][STR];

    const int tid = threadIdx.x;
    const int row0 = blockIdx.y * 128, col0 = blockIdx.x * 128;
    const int lane = tid & 31, wid = tid >> 5;
    const int wm = wid >> 2, wn = wid & 3;

    float acc[16][4];
#pragma unroll
    for (int i = 0; i < 16; i++)
#pragma unroll
        for (int j = 0; j < 4; j++) acc[i][j] = 0.0f;

    const int srow = tid >> 1, sseg = (tid & 1) * 2;

    auto stage = [&](int buf, int kt) {
        const int k16 = kt * 16;
#pragma unroll
        for (int q = 0; q < 2; q++) {
            int seg = sseg + q;
            cp16(s2u(&As[buf][srow][seg * 8]), &g_attnb[(size_t)(row0 + srow) * 256 + k16 + seg * 4]);
            cp16(s2u(&Bs[buf][srow][seg * 8]), &g_wproj_t[(size_t)(col0 + srow) * 256 + k16 + seg * 4]);
        }
    };

    stage(0, 0);
    cp_commit();

    const unsigned a_base = s2u(&As[0][0][0]);
    const unsigned b_base = s2u(&Bs[0][0][0]);
    const unsigned bufsz = 128 * STR * 2;
    const int a_row = wm * 64 + (lane & 15);
    const int a_colB = (lane >> 4) * 16;
    const int b_row = wn * 32 + ((lane >> 4) & 1) * 8 + (lane & 7);
    const int b_colB = ((lane >> 3) & 1) * 16;

#pragma unroll 1
    for (int t = 0; t < 16; t++) {
        const int buf = t & 1;
        cp_wait0();
        __syncthreads();
        if (t < 15) { stage(buf ^ 1, t + 1); cp_commit(); }
        const unsigned ab = a_base + buf * bufsz;
        const unsigned bb = b_base + buf * bufsz;
#pragma unroll
        for (int ks = 0; ks < 2; ks++) {
            unsigned afr[4][4], bfr[2][4];
#pragma unroll
            for (int mt = 0; mt < 4; mt++)
                ldsm4(afr[mt], ab + (unsigned)((a_row + mt * 16) * (STR * 2) + ks * 32 + a_colB));
#pragma unroll
            for (int n2 = 0; n2 < 2; n2++)
                ldsm4(bfr[n2], bb + (unsigned)((b_row + n2 * 16) * (STR * 2) + ks * 32 + b_colB));
#pragma unroll
            for (int mt = 0; mt < 4; mt++)
#pragma unroll
                for (int nt = 0; nt < 4; nt++)
                    mma_bf16(acc[mt * 4 + nt], afr[mt], &bfr[nt >> 1][(nt & 1) * 2]);
        }
        __syncthreads();
    }

#pragma unroll
    for (int mt = 0; mt < 4; mt++) {
#pragma unroll
        for (int half = 0; half < 2; half++) {
            int r = row0 + wm * 64 + mt * 16 + (lane >> 2) + half * 8;
            size_t pix = (size_t)row_to_pixel(r) * CDIM;
#pragma unroll
            for (int nt = 0; nt < 4; nt++) {
                int c = col0 + wn * 32 + nt * 8 + (lane & 3) * 2;
                float2 bv2 = *reinterpret_cast<const float2*>(bias + c);
                float2 xv  = *reinterpret_cast<const float2*>(x + pix + c);
                float2 ov;
                ov.x = xv.x + acc[mt * 4 + nt][half * 2]     + bv2.x;
                ov.y = xv.y + acc[mt * 4 + nt][half * 2 + 1] + bv2.y;
                *reinterpret_cast<float2*>(&out[pix + c]) = ov;
            }
        }
    }
}

extern "C" void kernel_launch(void* const* d_in, const int* in_sizes, int n_in,
                              void* d_out, int out_size) {
    const float* x      = (const float*)d_in[0];
    const float* qkv_w  = (const float*)d_in[1];
    const float* qkv_b  = (const float*)d_in[2];
    const float* proj_w = (const float*)d_in[3];
    const float* proj_b = (const float*)d_in[4];
    const float* table  = (const float*)d_in[5];
    float* out = (float*)d_out;

    cvt_x_kernel<<<(NPIX * 512 / 4) / 256, 256>>>(x);
    wtrans_kernel<<<1536, 256>>>(qkv_w, 1536, 0);
    wtrans_kernel<<<512, 256>>>(proj_w, 512, 1);

    qkv_gemm<<<dim3(12, 392), 256>>>(qkv_b);
    attn_kernel<<<NWIN * HEADS, 256>>>(table);
    proj_gemm<<<dim3(4, 392), 256>>>(x, proj_b, out);
}